// round 15
// baseline (speedup 1.0000x reference)
#include <cuda_runtime.h>
#include <cuda_fp16.h>
#include <cstdint>

#define BM 128
#define BN 128
#define KC 32
#define RSB 80                        // smem row stride bytes (32 f16 + 16B pad)
#define TBYTES (BM * RSB)             // 10240 per tile
#define SBYTES (2 * TBYTES)           // A + B per stage = 20480
#define NIT 16                        // 16 x KC=32 = K=512
// stage1: 3-stage pipeline (proven, L2/L1-hot operands)
#define S1_STAGES 3
#define S1_SMEM (S1_STAGES * SBYTES)  // 61440
// stage2: 4-stage pipeline (tmp B-tiles can miss to DRAM; more latency cover)
#define S2_STAGES 4
#define S2_SMEM (S2_STAGES * SBYTES)  // 81920

// ---------------- fp16 operand storage ----------------
__device__ __align__(16) __half g_x1h[2048 * 512];
__device__ __align__(16) __half g_x2h[2048 * 512];
__device__ __align__(16) __half g_wh[64ull * 512 * 512];   // [k][q][p] transposed
__device__ __align__(16) __half g_th[2048ull * 32768];     // tmp [bi][k*512+q]

// ---------------- asm helpers ----------------
static __device__ __forceinline__ uint32_t s2u(const void* p) {
    uint32_t a;
    asm("{ .reg .u64 t; cvta.to.shared.u64 t, %1; cvt.u32.u64 %0, t; }" : "=r"(a) : "l"(p));
    return a;
}
#define CP16CG(dst, src) \
    asm volatile("cp.async.cg.shared.global [%0], [%1], 16;" :: "r"(dst), "l"(src) : "memory")
#define CP16CA(dst, src) \
    asm volatile("cp.async.ca.shared.global [%0], [%1], 16;" :: "r"(dst), "l"(src) : "memory")
#define CP_COMMIT()  asm volatile("cp.async.commit_group;" ::: "memory")
#define CP_WAIT_1()  asm volatile("cp.async.wait_group 1;" ::: "memory")
#define CP_WAIT_2()  asm volatile("cp.async.wait_group 2;" ::: "memory")
#define LDSM4(r0, r1, r2, r3, addr) \
    asm volatile("ldmatrix.sync.aligned.m8n8.x4.shared.b16 {%0,%1,%2,%3}, [%4];" \
                 : "=r"(r0), "=r"(r1), "=r"(r2), "=r"(r3) : "r"(addr))
#define MMA16816(d, a, b0, b1) \
    asm volatile("mma.sync.aligned.m16n8k16.row.col.f32.f16.f16.f32 " \
                 "{%0,%1,%2,%3}, {%4,%5,%6,%7}, {%8,%9}, {%0,%1,%2,%3};" \
                 : "+f"((d)[0]), "+f"((d)[1]), "+f"((d)[2]), "+f"((d)[3]) \
                 : "r"((a)[0]), "r"((a)[1]), "r"((a)[2]), "r"((a)[3]), "r"(b0), "r"(b1))

// GEMM compute phase for one iteration's stage buffer (R9-proven order).
#define COMPUTE_ITER(sb)                                                             \
    {                                                                                \
        uint32_t aBase = (sb) + (wm + lrow) * RSB + lh * 16;                         \
        uint32_t bBase = (sb) + TBYTES + (wn + lrow) * RSB + lh * 16;                \
        _Pragma("unroll")                                                            \
        for (int kk = 0; kk < 2; kk++) {                                             \
            uint32_t af[4][4], br[2][4];                                             \
            _Pragma("unroll")                                                        \
            for (int mi = 0; mi < 4; mi++)                                           \
                LDSM4(af[mi][0], af[mi][1], af[mi][2], af[mi][3],                    \
                      aBase + mi * 16 * RSB + kk * 32);                              \
            _Pragma("unroll")                                                        \
            for (int nb = 0; nb < 2; nb++)                                           \
                LDSM4(br[nb][0], br[nb][1], br[nb][2], br[nb][3],                    \
                      bBase + nb * 16 * RSB + kk * 32);                              \
            _Pragma("unroll")                                                        \
            for (int mi = 0; mi < 4; mi++)                                           \
                _Pragma("unroll")                                                    \
                for (int ni = 0; ni < 4; ni++)                                       \
                    MMA16816(acc[mi][ni], af[mi],                                    \
                             br[ni >> 1][ni & 1], br[ni >> 1][(ni & 1) + 2]);        \
        }                                                                            \
    }

// ---------------- preprocessing ----------------
// 4 elems/thread, float4 loads, half2 stores.
__global__ void __launch_bounds__(256) cvt_x_kernel(const float* __restrict__ x1,
                                                    const float* __restrict__ x2) {
    int i = blockIdx.x * 1024 + threadIdx.x * 4;
    const float* x = blockIdx.y ? x2 : x1;
    __half* h = blockIdx.y ? g_x2h : g_x1h;
    float4 v = *(const float4*)&x[i];
    __half2* d = (__half2*)&h[i];
    d[0] = __floats2half2_rn(v.x, v.y);
    d[1] = __floats2half2_rn(v.z, v.w);
}

// W[k][p][q] -> g_wh[k][q][p]: 64p x 32q tiles, coalesced half2 stores.
__global__ void __launch_bounds__(256) cvtW_kernel(const float* __restrict__ w) {
    __shared__ float tile[64][33];    // [p_local][q_local]
    int k = blockIdx.z, p0 = blockIdx.y * 64, q0 = blockIdx.x * 32;
    int tx = threadIdx.x & 31, ty = threadIdx.x >> 5;   // ty 0..7
    const float* src = w + ((size_t)k * 512 + p0) * 512 + q0;
#pragma unroll
    for (int r = 0; r < 64; r += 8)
        tile[ty + r][tx] = src[(size_t)(ty + r) * 512 + tx];
    __syncthreads();
    __half2* dst = (__half2*)(g_wh + ((size_t)k * 512 + q0) * 512 + p0);
#pragma unroll
    for (int rr = 0; rr < 32; rr += 8) {
        int ql = ty + rr;
        __half2 v = __floats2half2_rn(tile[2 * tx][ql], tile[2 * tx + 1][ql]);
        dst[(size_t)ql * 256 + tx] = v;
    }
}

// ---------------- stage 1: tmp[bi, k*512+q] = sum_p x1h[bi,p] Wh[k,p,q] ----------------
__global__ void __launch_bounds__(256, 2) stage1_kernel() {
    extern __shared__ __align__(16) char sm[];
    uint32_t sbase = s2u(sm);
    int t = threadIdx.x, l = t & 31, w = t >> 5;
    int m0 = blockIdx.x * BM, n0 = blockIdx.y * BN;
    int wm = (w >> 2) * 64, wn = (w & 3) * 32;
    int lrow = l & 15, lh = l >> 4;

    uint32_t aOff[2], aDst[2], bOff[2], bDst[2];
#pragma unroll
    for (int i = 0; i < 2; i++) {
        int o = t * 2 + i, r = o >> 2, c = o & 3;
        aOff[i] = (uint32_t)(m0 + r) * 512 + c * 8;
        aDst[i] = r * RSB + c * 16;
        int ng = n0 + r, kf = ng >> 9, q = ng & 511;
        bOff[i] = (uint32_t)(kf * 512 + q) * 512 + c * 8;
        bDst[i] = TBYTES + r * RSB + c * 16;
    }
    float acc[4][4][4];
#pragma unroll
    for (int a = 0; a < 4; a++)
#pragma unroll
        for (int b = 0; b < 4; b++)
#pragma unroll
            for (int c = 0; c < 4; c++) acc[a][b][c] = 0.f;

    auto _issue = [&](int it) {
        uint32_t ko = it * KC;
        uint32_t sb = sbase + (it % S1_STAGES) * SBYTES;
#pragma unroll
        for (int i = 0; i < 2; i++) {
            CP16CG(sb + aDst[i], g_x1h + aOff[i] + ko);
            CP16CA(sb + bDst[i], g_wh + bOff[i] + ko);   // shared with co-resident CTA
        }
        CP_COMMIT();
    };

    _issue(0); _issue(1);
#pragma unroll 1
    for (int it = 0; it < NIT; it++) {
        CP_WAIT_1();
        __syncthreads();
        if (it + 2 < NIT) _issue(it + 2); else CP_COMMIT();
        COMPUTE_ITER(sbase + (it % S1_STAGES) * SBYTES)
    }

    // epilogue: fp16-convert C -> g_th
#pragma unroll
    for (int mi = 0; mi < 4; mi++) {
        int r0 = m0 + wm + mi * 16 + (l >> 2);
#pragma unroll
        for (int ni = 0; ni < 4; ni++) {
            int c = n0 + wn + ni * 8 + (l & 3) * 2;
#pragma unroll
            for (int hrow = 0; hrow < 2; hrow++) {
                size_t idx = (size_t)(r0 + hrow * 8) * 32768 + c;
                __half2 hh;
                hh.x = __float2half_rn(acc[mi][ni][hrow * 2]);
                hh.y = __float2half_rn(acc[mi][ni][hrow * 2 + 1]);
                *(__half2*)&g_th[idx] = hh;
            }
        }
    }
}

// ---------------- stage 2: out[b,i0+il,j,k] = sum_q x2h[bj,q] th[bi,k,q] + bias ------
__global__ void __launch_bounds__(256, 2) stage2_kernel(const float* __restrict__ bias,
                                                        float* __restrict__ out) {
    extern __shared__ __align__(16) char sm[];
    __shared__ float s_bias[64];
    uint32_t sbase = s2u(sm);
    int t = threadIdx.x, l = t & 31, w = t >> 5;
    int bz = blockIdx.z;
    int b = bz >> 6, i0 = (bz & 63) * 4;
    int j0 = blockIdx.x * BM, n0 = blockIdx.y * BN;
    int wm = (w >> 2) * 64, wn = (w & 3) * 32;
    int lrow = l & 15, lh = l >> 4;
    if (t < 64) s_bias[t] = bias[t];

    uint32_t aOff[2], aDst[2], bOff[2], bDst[2];
#pragma unroll
    for (int i = 0; i < 2; i++) {
        int o = t * 2 + i, r = o >> 2, c = o & 3;
        aOff[i] = (uint32_t)(b * 256 + j0 + r) * 512 + c * 8;
        aDst[i] = r * RSB + c * 16;
        int ng = n0 + r, il = ng >> 6, k = ng & 63;
        bOff[i] = (uint32_t)(b * 256 + i0 + il) * 32768 + k * 512 + c * 8;
        bDst[i] = TBYTES + r * RSB + c * 16;
    }
    float acc[4][4][4];
#pragma unroll
    for (int a = 0; a < 4; a++)
#pragma unroll
        for (int bb = 0; bb < 4; bb++)
#pragma unroll
            for (int c = 0; c < 4; c++) acc[a][bb][c] = 0.f;

    auto _issue = [&](int it) {
        uint32_t ko = it * KC;
        uint32_t sb = sbase + (it % S2_STAGES) * SBYTES;
#pragma unroll
        for (int i = 0; i < 2; i++) {
            CP16CG(sb + aDst[i], g_x2h + aOff[i] + ko);
            CP16CA(sb + bDst[i], g_th + bOff[i] + ko);   // shared with co-resident CTA
        }
        CP_COMMIT();
    };

    _issue(0); _issue(1); _issue(2);
#pragma unroll 1
    for (int it = 0; it < NIT; it++) {
        CP_WAIT_2();
        __syncthreads();
        if (it + 3 < NIT) _issue(it + 3); else CP_COMMIT();
        COMPUTE_ITER(sbase + (it % S2_STAGES) * SBYTES)
    }

    // epilogue: add bias, streaming stores (don't evict g_th from L2)
#pragma unroll
    for (int mi = 0; mi < 4; mi++) {
        int j = j0 + wm + mi * 16 + (l >> 2);
#pragma unroll
        for (int ni = 0; ni < 4; ni++) {
            int c = n0 + wn + ni * 8 + (l & 3) * 2;
            int il = c >> 6, k = c & 63;
            float bk0 = s_bias[k], bk1 = s_bias[k + 1];
#pragma unroll
            for (int hrow = 0; hrow < 2; hrow++) {
                size_t idx = ((size_t)(b * 256 + i0 + il) * 256 + j + hrow * 8) * 64 + k;
                float2 v = make_float2(acc[mi][ni][hrow * 2] + bk0,
                                       acc[mi][ni][hrow * 2 + 1] + bk1);
                __stcs((float2*)&out[idx], v);
            }
        }
    }
}

// ---------------- host ----------------
extern "C" void kernel_launch(void* const* d_in, const int* in_sizes, int n_in,
                              void* d_out, int out_size)
{
    const float* x1   = (const float*)d_in[0];
    const float* x2   = (const float*)d_in[1];
    const float* w    = (const float*)d_in[2];
    const float* bias = (const float*)d_in[3];
    float* out        = (float*)d_out;

    cudaFuncSetAttribute(stage1_kernel, cudaFuncAttributeMaxDynamicSharedMemorySize, S1_SMEM);
    cudaFuncSetAttribute(stage2_kernel, cudaFuncAttributeMaxDynamicSharedMemorySize, S2_SMEM);

    cvt_x_kernel<<<dim3(1024, 2), 256>>>(x1, x2);
    cvtW_kernel<<<dim3(16, 8, 64), 256>>>(w);

    stage1_kernel<<<dim3(16, 256), 256, S1_SMEM>>>();
    stage2_kernel<<<dim3(2, 2, 512), 256, S2_SMEM>>>(bias, out);
}

// round 17
// speedup vs baseline: 1.0074x; 1.0074x over previous
#include <cuda_runtime.h>
#include <cuda_fp16.h>
#include <cstdint>

#define BM 128
#define BN 128
#define KC 32
#define RSB 80                        // smem row stride bytes (32 f16 + 16B pad)
#define TBYTES (BM * RSB)             // 10240 per tile
#define SBYTES (2 * TBYTES)           // A + B per stage = 20480
#define STAGES 3
#define SMEM_DYN (STAGES * SBYTES)    // 61440
#define NIT 16                        // 16 x KC=32 = K=512

// ---------------- fp16 operand storage ----------------
__device__ __align__(16) __half g_x1h[2048 * 512];
__device__ __align__(16) __half g_x2h[2048 * 512];
__device__ __align__(16) __half g_wh[64ull * 512 * 512];   // [k][q][p] transposed
__device__ __align__(16) __half g_th[2048ull * 32768];     // tmp [bi][k*512+q]

// ---------------- asm helpers ----------------
static __device__ __forceinline__ uint32_t s2u(const void* p) {
    uint32_t a;
    asm("{ .reg .u64 t; cvta.to.shared.u64 t, %1; cvt.u32.u64 %0, t; }" : "=r"(a) : "l"(p));
    return a;
}
// A operands: L2-only (.cg, no same-SM reuse). B operands: L1-allocating (.ca) —
// the co-resident CTA (adjacent id, same B tile) hits L1.  (R13-proven.)
#define CP16CG(dst, src) \
    asm volatile("cp.async.cg.shared.global [%0], [%1], 16;" :: "r"(dst), "l"(src) : "memory")
#define CP16CA(dst, src) \
    asm volatile("cp.async.ca.shared.global [%0], [%1], 16;" :: "r"(dst), "l"(src) : "memory")
#define CP_COMMIT() asm volatile("cp.async.commit_group;" ::: "memory")
#define CP_WAIT()   asm volatile("cp.async.wait_group 1;" ::: "memory")
#define LDSM4(r0, r1, r2, r3, addr) \
    asm volatile("ldmatrix.sync.aligned.m8n8.x4.shared.b16 {%0,%1,%2,%3}, [%4];" \
                 : "=r"(r0), "=r"(r1), "=r"(r2), "=r"(r3) : "r"(addr))
#define MMA16816(d, a, b0, b1) \
    asm volatile("mma.sync.aligned.m16n8k16.row.col.f32.f16.f16.f32 " \
                 "{%0,%1,%2,%3}, {%4,%5,%6,%7}, {%8,%9}, {%0,%1,%2,%3};" \
                 : "+f"((d)[0]), "+f"((d)[1]), "+f"((d)[2]), "+f"((d)[3]) \
                 : "r"((a)[0]), "r"((a)[1]), "r"((a)[2]), "r"((a)[3]), "r"(b0), "r"(b1))

// GEMM core: 128x128 CTA tile, warp tile 64x32 (2Mx4N warps), KC=32,
// 3-stage cp.async pipeline, single fp16 MMA pass per k-chunk.  (R9/R13-proven.)
#define GEMM_CORE()                                                                  \
    {                                                                                \
        _issue(0);                                                                   \
        _issue(1);                                                                   \
        _Pragma("unroll 1")                                                          \
        for (int it = 0; it < NIT; it++) {                                           \
            CP_WAIT();                                                               \
            __syncthreads();                                                         \
            if (it + 2 < NIT) _issue(it + 2); else CP_COMMIT();                      \
            uint32_t sb = sbase + (it % STAGES) * SBYTES;                            \
            uint32_t aBase = sb + (wm + lrow) * RSB + lh * 16;                       \
            uint32_t bBase = sb + TBYTES + (wn + lrow) * RSB + lh * 16;              \
            _Pragma("unroll")                                                        \
            for (int kk = 0; kk < 2; kk++) {                                         \
                uint32_t af[4][4], br[2][4];                                         \
                _Pragma("unroll")                                                    \
                for (int mi = 0; mi < 4; mi++)                                       \
                    LDSM4(af[mi][0], af[mi][1], af[mi][2], af[mi][3],                \
                          aBase + mi * 16 * RSB + kk * 32);                          \
                _Pragma("unroll")                                                    \
                for (int nb = 0; nb < 2; nb++)                                       \
                    LDSM4(br[nb][0], br[nb][1], br[nb][2], br[nb][3],                \
                          bBase + nb * 16 * RSB + kk * 32);                          \
                _Pragma("unroll")                                                    \
                for (int mi = 0; mi < 4; mi++)                                       \
                    _Pragma("unroll")                                                \
                    for (int ni = 0; ni < 4; ni++)                                   \
                        MMA16816(acc[mi][ni], af[mi],                                \
                                 br[ni >> 1][ni & 1], br[ni >> 1][(ni & 1) + 2]);    \
            }                                                                        \
        }                                                                            \
    }

// ---------------- preprocessing ----------------
// 4 elems/thread, float4 loads, half2 stores.
__global__ void __launch_bounds__(256) cvt_x_kernel(const float* __restrict__ x1,
                                                    const float* __restrict__ x2) {
    int i = blockIdx.x * 1024 + threadIdx.x * 4;
    const float* x = blockIdx.y ? x2 : x1;
    __half* h = blockIdx.y ? g_x2h : g_x1h;
    float4 v = *(const float4*)&x[i];
    __half2* d = (__half2*)&h[i];
    d[0] = __floats2half2_rn(v.x, v.y);
    d[1] = __floats2half2_rn(v.z, v.w);
}

// W[k][p][q] -> g_wh[k][q][p]: 64p x 32q tiles, coalesced half2 stores.
__global__ void __launch_bounds__(256) cvtW_kernel(const float* __restrict__ w) {
    __shared__ float tile[64][33];    // [p_local][q_local]
    int k = blockIdx.z, p0 = blockIdx.y * 64, q0 = blockIdx.x * 32;
    int tx = threadIdx.x & 31, ty = threadIdx.x >> 5;   // ty 0..7
    const float* src = w + ((size_t)k * 512 + p0) * 512 + q0;
#pragma unroll
    for (int r = 0; r < 64; r += 8)
        tile[ty + r][tx] = src[(size_t)(ty + r) * 512 + tx];
    __syncthreads();
    __half2* dst = (__half2*)(g_wh + ((size_t)k * 512 + q0) * 512 + p0);
#pragma unroll
    for (int rr = 0; rr < 32; rr += 8) {
        int ql = ty + rr;
        __half2 v = __floats2half2_rn(tile[2 * tx][ql], tile[2 * tx + 1][ql]);
        dst[(size_t)ql * 256 + tx] = v;
    }
}

// ---------------- stage 1: tmp[bi, k*512+q] = sum_p x1h[bi,p] Wh[k,p,q] ----------------
__global__ void __launch_bounds__(256, 2) stage1_kernel() {
    extern __shared__ __align__(16) char sm[];
    uint32_t sbase = s2u(sm);
    int t = threadIdx.x, l = t & 31, w = t >> 5;
    int m0 = blockIdx.x * BM, n0 = blockIdx.y * BN;
    int wm = (w >> 2) * 64, wn = (w & 3) * 32;
    int lrow = l & 15, lh = l >> 4;

    uint32_t aOff[2], aDst[2], bOff[2], bDst[2];
#pragma unroll
    for (int i = 0; i < 2; i++) {
        int o = t * 2 + i, r = o >> 2, c = o & 3;
        aOff[i] = (uint32_t)(m0 + r) * 512 + c * 8;
        aDst[i] = r * RSB + c * 16;
        int ng = n0 + r, kf = ng >> 9, q = ng & 511;
        bOff[i] = (uint32_t)(kf * 512 + q) * 512 + c * 8;
        bDst[i] = TBYTES + r * RSB + c * 16;
    }
    float acc[4][4][4];
#pragma unroll
    for (int a = 0; a < 4; a++)
#pragma unroll
        for (int b = 0; b < 4; b++)
#pragma unroll
            for (int c = 0; c < 4; c++) acc[a][b][c] = 0.f;

    auto _issue = [&](int it) {
        uint32_t ko = it * KC;
        uint32_t sb = sbase + (it % STAGES) * SBYTES;
#pragma unroll
        for (int i = 0; i < 2; i++) {
            CP16CG(sb + aDst[i], g_x1h + aOff[i] + ko);
            CP16CA(sb + bDst[i], g_wh + bOff[i] + ko);   // shared with co-resident CTA
        }
        CP_COMMIT();
    };

    GEMM_CORE()

    // epilogue: fp16-convert C -> g_th
#pragma unroll
    for (int mi = 0; mi < 4; mi++) {
        int r0 = m0 + wm + mi * 16 + (l >> 2);
#pragma unroll
        for (int ni = 0; ni < 4; ni++) {
            int c = n0 + wn + ni * 8 + (l & 3) * 2;
#pragma unroll
            for (int hrow = 0; hrow < 2; hrow++) {
                size_t idx = (size_t)(r0 + hrow * 8) * 32768 + c;
                __half2 hh;
                hh.x = __float2half_rn(acc[mi][ni][hrow * 2]);
                hh.y = __float2half_rn(acc[mi][ni][hrow * 2 + 1]);
                *(__half2*)&g_th[idx] = hh;
            }
        }
    }
}

// ---------------- stage 2: out[b,i0+il,j,k] = sum_q x2h[bj,q] th[bi,k,q] + bias ------
__global__ void __launch_bounds__(256, 2) stage2_kernel(const float* __restrict__ bias,
                                                        float* __restrict__ out) {
    extern __shared__ __align__(16) char sm[];
    __shared__ float s_bias[64];
    uint32_t sbase = s2u(sm);
    int t = threadIdx.x, l = t & 31, w = t >> 5;
    int bz = blockIdx.z;
    int b = bz >> 6, i0 = (bz & 63) * 4;
    int j0 = blockIdx.x * BM, n0 = blockIdx.y * BN;
    int wm = (w >> 2) * 64, wn = (w & 3) * 32;
    int lrow = l & 15, lh = l >> 4;
    if (t < 64) s_bias[t] = bias[t];

    uint32_t aOff[2], aDst[2], bOff[2], bDst[2];
#pragma unroll
    for (int i = 0; i < 2; i++) {
        int o = t * 2 + i, r = o >> 2, c = o & 3;
        aOff[i] = (uint32_t)(b * 256 + j0 + r) * 512 + c * 8;
        aDst[i] = r * RSB + c * 16;
        int ng = n0 + r, il = ng >> 6, k = ng & 63;
        bOff[i] = (uint32_t)(b * 256 + i0 + il) * 32768 + k * 512 + c * 8;
        bDst[i] = TBYTES + r * RSB + c * 16;
    }
    float acc[4][4][4];
#pragma unroll
    for (int a = 0; a < 4; a++)
#pragma unroll
        for (int bb = 0; bb < 4; bb++)
#pragma unroll
            for (int c = 0; c < 4; c++) acc[a][bb][c] = 0.f;

    auto _issue = [&](int it) {
        uint32_t ko = it * KC;
        uint32_t sb = sbase + (it % STAGES) * SBYTES;
#pragma unroll
        for (int i = 0; i < 2; i++) {
            CP16CG(sb + aDst[i], g_x2h + aOff[i] + ko);
            CP16CA(sb + bDst[i], g_th + bOff[i] + ko);   // shared with co-resident CTA
        }
        CP_COMMIT();
    };

    GEMM_CORE()

    // epilogue: add bias, streaming stores (don't evict g_th from L2)
#pragma unroll
    for (int mi = 0; mi < 4; mi++) {
        int j = j0 + wm + mi * 16 + (l >> 2);
#pragma unroll
        for (int ni = 0; ni < 4; ni++) {
            int c = n0 + wn + ni * 8 + (l & 3) * 2;
            int il = c >> 6, k = c & 63;
            float bk0 = s_bias[k], bk1 = s_bias[k + 1];
#pragma unroll
            for (int hrow = 0; hrow < 2; hrow++) {
                size_t idx = ((size_t)(b * 256 + i0 + il) * 256 + j + hrow * 8) * 64 + k;
                float2 v = make_float2(acc[mi][ni][hrow * 2] + bk0,
                                       acc[mi][ni][hrow * 2 + 1] + bk1);
                __stcs((float2*)&out[idx], v);
            }
        }
    }
}

// ---------------- host ----------------
extern "C" void kernel_launch(void* const* d_in, const int* in_sizes, int n_in,
                              void* d_out, int out_size)
{
    const float* x1   = (const float*)d_in[0];
    const float* x2   = (const float*)d_in[1];
    const float* w    = (const float*)d_in[2];
    const float* bias = (const float*)d_in[3];
    float* out        = (float*)d_out;

    cudaFuncSetAttribute(stage1_kernel, cudaFuncAttributeMaxDynamicSharedMemorySize, SMEM_DYN);
    cudaFuncSetAttribute(stage2_kernel, cudaFuncAttributeMaxDynamicSharedMemorySize, SMEM_DYN);

    cvt_x_kernel<<<dim3(1024, 2), 256>>>(x1, x2);
    cvtW_kernel<<<dim3(16, 8, 64), 256>>>(w);

    stage1_kernel<<<dim3(16, 256), 256, SMEM_DYN>>>();
    stage2_kernel<<<dim3(2, 2, 512), 256, SMEM_DYN>>>(bias, out);
}